// round 2
// baseline (speedup 1.0000x reference)
#include <cuda_runtime.h>

#define BB 8
#define NN 8192
#define NP 2048
#define KK 16
#define FF 64
#define PP (BB*NP*KK)
#define PTSN (BB*NN)

// ---- scratch (device globals; allocation is forbidden) ----
__device__ float g_Z1[(size_t)PTSN*FF];     // per-point W1[:,3:]@feat  (16MB)
__device__ float g_buf[(size_t)PP*FF];      // y1/y2 channel-major      (64MB)
__device__ int   g_fps[BB*NP];
__device__ int   g_knn[PP];
__device__ float g_stats[256];              // [which*128 + {sum:0..63, sq:64..127}]
__device__ float g_sc[256];                 // [which*128 + {scale, shift}]

__global__ void k_zero() { g_stats[threadIdx.x] = 0.f; }

// ---------------- FPS: one block per batch ----------------
__global__ __launch_bounds__(1024) void k_fps(const float* __restrict__ xyz) {
    extern __shared__ float sm[];
    float* sx = sm; float* sy = sm + NN; float* sz = sm + 2*NN;
    float* rv = sm + 3*NN; int* ri = (int*)(rv + 32); float* sp = (float*)(ri + 32);

    int b = blockIdx.x, tid = threadIdx.x, base = tid*8;
    const float* X = xyz + (size_t)b*3*NN;
    float x[8], y[8], z[8], dmin[8];
    #pragma unroll
    for (int i = 0; i < 8; i += 4) {
        float4 vx = *(const float4*)(X + base + i);
        float4 vy = *(const float4*)(X + NN + base + i);
        float4 vz = *(const float4*)(X + 2*NN + base + i);
        x[i]=vx.x; x[i+1]=vx.y; x[i+2]=vx.z; x[i+3]=vx.w;
        y[i]=vy.x; y[i+1]=vy.y; y[i+2]=vy.z; y[i+3]=vy.w;
        z[i]=vz.x; z[i+1]=vz.y; z[i+2]=vz.z; z[i+3]=vz.w;
    }
    #pragma unroll
    for (int i = 0; i < 8; i++) {
        dmin[i] = 1e10f;
        sx[base+i] = x[i]; sy[base+i] = y[i]; sz[base+i] = z[i];
    }
    if (tid == 0) { sp[0]=X[0]; sp[1]=X[NN]; sp[2]=X[2*NN]; g_fps[b*NP]=0; }
    __syncthreads();

    for (int t = 1; t < NP; t++) {
        float px = sp[0], py = sp[1], pz = sp[2];
        float bestv = -1.f; int besti = 0;
        #pragma unroll
        for (int i = 0; i < 8; i++) {
            float dx = __fsub_rn(x[i], px);
            float dy = __fsub_rn(y[i], py);
            float dz = __fsub_rn(z[i], pz);
            float d  = __fadd_rn(__fadd_rn(__fmul_rn(dx,dx), __fmul_rn(dy,dy)), __fmul_rn(dz,dz));
            dmin[i] = fminf(dmin[i], d);
            if (dmin[i] > bestv) { bestv = dmin[i]; besti = base + i; }
        }
        #pragma unroll
        for (int off = 16; off; off >>= 1) {
            float ov = __shfl_down_sync(0xffffffffu, bestv, off);
            int   oi = __shfl_down_sync(0xffffffffu, besti, off);
            if (ov > bestv || (ov == bestv && oi < besti)) { bestv = ov; besti = oi; }
        }
        if ((tid & 31) == 0) { rv[tid>>5] = bestv; ri[tid>>5] = besti; }
        __syncthreads();
        if (tid < 32) {
            bestv = rv[tid]; besti = ri[tid];
            #pragma unroll
            for (int off = 16; off; off >>= 1) {
                float ov = __shfl_down_sync(0xffffffffu, bestv, off);
                int   oi = __shfl_down_sync(0xffffffffu, besti, off);
                if (ov > bestv || (ov == bestv && oi < besti)) { bestv = ov; besti = oi; }
            }
            if (tid == 0) {
                g_fps[b*NP + t] = besti;
                sp[0] = sx[besti]; sp[1] = sy[besti]; sp[2] = sz[besti];
            }
        }
        __syncthreads();
    }
}

// ---------------- gather new_xyz into output ----------------
__global__ void k_nx(const float* __restrict__ xyz, float* __restrict__ out) {
    int i = blockIdx.x*256 + threadIdx.x;          // 0..BB*NP-1
    int b = i >> 11, q = i & 2047, n = g_fps[i];
    #pragma unroll
    for (int c = 0; c < 3; c++)
        out[((size_t)b*3 + c)*NP + q] = xyz[((size_t)b*3 + c)*NN + n];
}

// ---------------- KNN ----------------
__global__ __launch_bounds__(128) void k_knn(const float* __restrict__ xyz) {
    extern __shared__ float4 s4[];                  // NN (x,y,z,|x|^2)
    int b = blockIdx.y;
    const float* X = xyz + (size_t)b*3*NN;
    for (int j = threadIdx.x; j < NN; j += 128) {
        float xx = X[j], yy = X[NN+j], zz = X[2*NN+j];
        float r = __fadd_rn(__fadd_rn(__fmul_rn(xx,xx), __fmul_rn(yy,yy)), __fmul_rn(zz,zz));
        s4[j] = make_float4(xx, yy, zz, r);
    }
    __syncthreads();
    int q = blockIdx.x*128 + threadIdx.x;
    int qi = g_fps[b*NP + q];
    float qx = X[qi], qy = X[NN+qi], qz = X[2*NN+qi];
    float qq = __fadd_rn(__fadd_rn(__fmul_rn(qx,qx), __fmul_rn(qy,qy)), __fmul_rn(qz,qz));

    float bd[KK]; int bi[KK];
    #pragma unroll
    for (int s = 0; s < KK; s++) { bd[s] = 3.0e38f; bi[s] = 0x7fffffff; }
    float wv = 3.0e38f; int ws = 0;
    #pragma unroll 4
    for (int j = 0; j < NN; j++) {
        float4 c = s4[j];
        float dot = __fadd_rn(__fadd_rn(__fmul_rn(qx,c.x), __fmul_rn(qy,c.y)), __fmul_rn(qz,c.z));
        float d = __fsub_rn(__fadd_rn(qq, c.w), __fmul_rn(2.0f, dot));
        if (d < wv) {
            bd[ws] = d; bi[ws] = j;
            float nv = -3.0e38f; int ns = 0, ni = -1;
            #pragma unroll
            for (int s = 0; s < KK; s++)
                if (bd[s] > nv || (bd[s] == nv && bi[s] > ni)) { nv = bd[s]; ns = s; ni = bi[s]; }
            wv = nv; ws = ns;
        }
    }
    int* dst = g_knn + ((size_t)b*NP + q)*KK;
    #pragma unroll
    for (int s = 0; s < KK; s++) dst[s] = bi[s];
}

// ---------------- Z1 = W1[:,3:] @ points, per point ----------------
__global__ __launch_bounds__(128) void k_z1(const float* __restrict__ pts,
                                            const float* __restrict__ W1) {
    __shared__ float w[FF*FF];
    int tid = threadIdx.x;
    for (int i = tid; i < FF*FF; i += 128) w[i] = W1[(i>>6)*67 + 3 + (i&63)];
    __syncthreads();
    int p = blockIdx.x*128 + tid;                  // 0..PTSN-1
    int b = p >> 13, n = p & (NN-1);
    float xv[FF];
    #pragma unroll
    for (int f = 0; f < FF; f++) xv[f] = pts[((size_t)b*FF + f)*NN + n];
    float* zr = g_Z1 + (size_t)p*FF;
    for (int o = 0; o < FF; o += 4) {
        float a0=0.f, a1=0.f, a2=0.f, a3=0.f;
        #pragma unroll
        for (int f = 0; f < FF; f++) {
            float xf = xv[f];
            a0 = fmaf(w[(o+0)*FF+f], xf, a0);
            a1 = fmaf(w[(o+1)*FF+f], xf, a1);
            a2 = fmaf(w[(o+2)*FF+f], xf, a2);
            a3 = fmaf(w[(o+3)*FF+f], xf, a3);
        }
        *(float4*)(zr + o) = make_float4(a0, a1, a2, a3);
    }
}

// ---------------- pass1: y1 -> g_buf channel-major ----------------
__global__ __launch_bounds__(128) void k_p1(const float* __restrict__ xyz,
                                            const float* __restrict__ W1,
                                            const float* __restrict__ b1,
                                            const float* __restrict__ nxyz) {
    __shared__ float w0[64], w1s[64], w2s[64], bb[64];
    int tid = threadIdx.x;
    if (tid < 64) {
        w0[tid]  = W1[tid*67 + 0]; w1s[tid] = W1[tid*67 + 1];
        w2s[tid] = W1[tid*67 + 2]; bb[tid]  = b1[tid];
    }
    __syncthreads();
    int pos = blockIdx.x*128 + tid;
    int b = pos >> 15, q = (pos >> 4) & 2047, n = g_knn[pos];
    float cx = nxyz[((size_t)b*3+0)*NP+q], cy = nxyz[((size_t)b*3+1)*NP+q], cz = nxyz[((size_t)b*3+2)*NP+q];
    const float* X = xyz + (size_t)b*3*NN;
    float dx = X[n]-cx, dy = X[NN+n]-cy, dz = X[2*NN+n]-cz;
    const float4* zr = (const float4*)(g_Z1 + (size_t)(b*NN + n)*FF);
    #pragma unroll
    for (int i = 0; i < 16; i++) {
        float4 v = zr[i]; int o = 4*i;
        g_buf[(size_t)(o+0)*PP+pos] = fmaf(w2s[o+0],dz, fmaf(w1s[o+0],dy, fmaf(w0[o+0],dx, v.x+bb[o+0])));
        g_buf[(size_t)(o+1)*PP+pos] = fmaf(w2s[o+1],dz, fmaf(w1s[o+1],dy, fmaf(w0[o+1],dx, v.y+bb[o+1])));
        g_buf[(size_t)(o+2)*PP+pos] = fmaf(w2s[o+2],dz, fmaf(w1s[o+2],dy, fmaf(w0[o+2],dx, v.z+bb[o+2])));
        g_buf[(size_t)(o+3)*PP+pos] = fmaf(w2s[o+3],dz, fmaf(w1s[o+3],dy, fmaf(w0[o+3],dx, v.w+bb[o+3])));
    }
}

// ---------------- per-channel sum/sumsq ----------------
__global__ __launch_bounds__(256) void k_st(int which) {
    int o = blockIdx.y;
    const float* src = g_buf + (size_t)o*PP + blockIdx.x*(PP/16);
    float s = 0.f, s2 = 0.f;
    for (int i = threadIdx.x; i < PP/16; i += 256) {
        float v = src[i]; s += v; s2 = fmaf(v, v, s2);
    }
    #pragma unroll
    for (int off = 16; off; off >>= 1) {
        s  += __shfl_down_sync(0xffffffffu, s,  off);
        s2 += __shfl_down_sync(0xffffffffu, s2, off);
    }
    __shared__ float as[8], as2[8];
    int wid = threadIdx.x >> 5;
    if ((threadIdx.x & 31) == 0) { as[wid] = s; as2[wid] = s2; }
    __syncthreads();
    if (threadIdx.x == 0) {
        float ts = 0.f, ts2 = 0.f;
        #pragma unroll
        for (int w = 0; w < 8; w++) { ts += as[w]; ts2 += as2[w]; }
        atomicAdd(g_stats + which*128 + o, ts);
        atomicAdd(g_stats + which*128 + 64 + o, ts2);
    }
}

__global__ void k_fin(const float* __restrict__ gam, const float* __restrict__ bet, int which) {
    int o = threadIdx.x;
    float m = g_stats[which*128 + o] / (float)PP;
    float v = g_stats[which*128 + 64 + o] / (float)PP - m*m;
    v = fmaxf(v, 0.f);
    float sc = gam[o] * rsqrtf(v + 1e-5f);
    g_sc[which*128 + o] = sc;
    g_sc[which*128 + 64 + o] = bet[o] - m*sc;
}

// ---------------- pass2: bn1+relu -> conv2 (in place) ----------------
__global__ __launch_bounds__(128) void k_p2(const float* __restrict__ W2, const float* __restrict__ b2) {
    __shared__ float w[64*64];
    __shared__ float sc[64], sh[64], bb[64];
    int tid = threadIdx.x;
    for (int i = tid; i < 64*64; i += 128) w[i] = W2[i];
    if (tid < 64) { sc[tid] = g_sc[tid]; sh[tid] = g_sc[64+tid]; bb[tid] = b2[tid]; }
    __syncthreads();
    int pos = blockIdx.x*128 + tid;
    float h[64];
    #pragma unroll
    for (int o = 0; o < 64; o++) {
        float y = g_buf[(size_t)o*PP + pos];
        h[o] = fmaxf(fmaf(y, sc[o], sh[o]), 0.f);
    }
    for (int o = 0; o < 64; o++) {
        float a = bb[o];
        const float* wr = w + o*64;
        #pragma unroll
        for (int f = 0; f < 64; f++) a = fmaf(wr[f], h[f], a);
        g_buf[(size_t)o*PP + pos] = a;
    }
}

// ---------------- pass3: bn2+relu -> conv3 -> max over K ----------------
__global__ __launch_bounds__(128) void k_p3(const float* __restrict__ W3, const float* __restrict__ b3,
                                            float* __restrict__ outf) {
    __shared__ float w[128*64];
    __shared__ float sc[64], sh[64], bb[128];
    int tid = threadIdx.x;
    for (int i = tid; i < 128*64; i += 128) w[i] = W3[i];
    if (tid < 64) { sc[tid] = g_sc[128+tid]; sh[tid] = g_sc[192+tid]; }
    if (tid < 128) bb[tid] = b3[tid];
    __syncthreads();
    int pos = blockIdx.x*128 + tid;
    float h[64];
    #pragma unroll
    for (int o = 0; o < 64; o++) {
        float y = g_buf[(size_t)o*PP + pos];
        h[o] = fmaxf(fmaf(y, sc[o], sh[o]), 0.f);
    }
    int lane = tid & 15;
    int q = pos >> 4;                // global query
    int b = q >> 11, qq = q & 2047;
    for (int c = 0; c < 4; c++) {
        float acc[32];
        #pragma unroll
        for (int o = 0; o < 32; o++) {
            const float* wr = w + (c*32 + o)*64;
            float a = bb[c*32 + o];
            #pragma unroll
            for (int f = 0; f < 64; f++) a = fmaf(wr[f], h[f], a);
            acc[o] = a;
        }
        #pragma unroll
        for (int o = 0; o < 32; o++) {
            float v = acc[o];
            #pragma unroll
            for (int off = 1; off < 16; off <<= 1)
                v = fmaxf(v, __shfl_xor_sync(0xffffffffu, v, off));
            acc[o] = v;
        }
        #pragma unroll
        for (int o = 0; o < 32; o++)
            if ((o & 15) == lane)
                outf[((size_t)b*128 + c*32 + o)*NP + qq] = acc[o];
    }
}

extern "C" void kernel_launch(void* const* d_in, const int* in_sizes, int n_in,
                              void* d_out, int out_size) {
    const float* xyz = (const float*)d_in[0];
    const float* pts = (const float*)d_in[1];
    const float* W1  = (const float*)d_in[2];
    const float* b1  = (const float*)d_in[3];
    const float* g1  = (const float*)d_in[4];
    const float* be1 = (const float*)d_in[5];
    const float* W2  = (const float*)d_in[6];
    const float* b2  = (const float*)d_in[7];
    const float* g2  = (const float*)d_in[8];
    const float* be2 = (const float*)d_in[9];
    const float* W3  = (const float*)d_in[10];
    const float* b3  = (const float*)d_in[11];
    float* out  = (float*)d_out;
    float* onx  = out;                       // new_xyz (B,3,NP)
    float* ofe  = out + (size_t)BB*3*NP;     // new_feat (B,128,NP)

    const int FPS_SM = (3*NN + 80)*4;
    const int KNN_SM = NN*16;
    cudaFuncSetAttribute(k_fps, cudaFuncAttributeMaxDynamicSharedMemorySize, FPS_SM);
    cudaFuncSetAttribute(k_knn, cudaFuncAttributeMaxDynamicSharedMemorySize, KNN_SM);

    k_zero<<<1, 256>>>();
    k_fps<<<BB, 1024, FPS_SM>>>(xyz);
    k_nx<<<(BB*NP)/256, 256>>>(xyz, onx);
    k_knn<<<dim3(NP/128, BB), 128, KNN_SM>>>(xyz);
    k_z1<<<PTSN/128, 128>>>(pts, W1);
    k_p1<<<PP/128, 128>>>(xyz, W1, b1, onx);
    k_st<<<dim3(16, 64), 256>>>(0);
    k_fin<<<1, 64>>>(g1, be1, 0);
    k_p2<<<PP/128, 128>>>(W2, b2);
    k_st<<<dim3(16, 64), 256>>>(1);
    k_fin<<<1, 64>>>(g2, be2, 1);
    k_p3<<<PP/128, 128>>>(W3, b3, ofe);
}

// round 3
// speedup vs baseline: 1.0415x; 1.0415x over previous
#include <cuda_runtime.h>

#define BB 8
#define NN 8192
#define NP 2048
#define KK 16
#define FF 64
#define PP (BB*NP*KK)
#define PTSN (BB*NN)

typedef unsigned long long ull;

// ---- scratch (device globals; allocation is forbidden) ----
__device__ float g_Z1[(size_t)PTSN*FF];
__device__ float g_buf[(size_t)PP*FF];
__device__ int   g_fps[BB*NP];
__device__ int   g_knn[PP];
__device__ float g_stats[256];
__device__ float g_sc[256];

__global__ void k_zero() { g_stats[threadIdx.x] = 0.f; }

// ---- packed f32x2 helpers (per-lane rounding identical to scalar rn ops) ----
__device__ __forceinline__ ull pk2(float lo, float hi) {
    ull r; asm("mov.b64 %0, {%1,%2};" : "=l"(r) : "f"(lo), "f"(hi)); return r;
}
__device__ __forceinline__ void upk2(ull v, float& lo, float& hi) {
    asm("mov.b64 {%0,%1}, %2;" : "=f"(lo), "=f"(hi) : "l"(v));
}
__device__ __forceinline__ ull add2(ull a, ull b) {
    ull r; asm("add.rn.f32x2 %0, %1, %2;" : "=l"(r) : "l"(a), "l"(b)); return r;
}
__device__ __forceinline__ ull mul2(ull a, ull b) {
    ull r; asm("mul.rn.f32x2 %0, %1, %2;" : "=l"(r) : "l"(a), "l"(b)); return r;
}

// ---------------- FPS: one block per batch, packed inner, 1 barrier/iter ----------------
__global__ __launch_bounds__(1024) void k_fps(const float* __restrict__ xyz) {
    extern __shared__ float sm[];
    float* sx = sm; float* sy = sm + NN; float* sz = sm + 2*NN;
    float* rv = sm + 3*NN;            // 64 floats (double-buffered 2x32)
    int*   ri = (int*)(rv + 64);      // 64 ints

    int b = blockIdx.x, tid = threadIdx.x, lane = tid & 31, wid = tid >> 5;
    int base = tid*8;
    const float* X = xyz + (size_t)b*3*NN;

    ull xp[4], yp[4], zp[4];
    float dmin[8];
    #pragma unroll
    for (int i = 0; i < 8; i += 4) {
        float4 vx = *(const float4*)(X + base + i);
        float4 vy = *(const float4*)(X + NN + base + i);
        float4 vz = *(const float4*)(X + 2*NN + base + i);
        xp[i/2]   = pk2(vx.x, vx.y); xp[i/2+1] = pk2(vx.z, vx.w);
        yp[i/2]   = pk2(vy.x, vy.y); yp[i/2+1] = pk2(vy.z, vy.w);
        zp[i/2]   = pk2(vz.x, vz.y); zp[i/2+1] = pk2(vz.z, vz.w);
        sx[base+i]=vx.x; sx[base+i+1]=vx.y; sx[base+i+2]=vx.z; sx[base+i+3]=vx.w;
        sy[base+i]=vy.x; sy[base+i+1]=vy.y; sy[base+i+2]=vy.z; sy[base+i+3]=vy.w;
        sz[base+i]=vz.x; sz[base+i+1]=vz.y; sz[base+i+2]=vz.z; sz[base+i+3]=vz.w;
    }
    #pragma unroll
    for (int i = 0; i < 8; i++) dmin[i] = 1e10f;

    float px = X[0], py = X[NN], pz = X[2*NN];
    if (tid == 0) g_fps[b*NP] = 0;
    __syncthreads();

    for (int t = 1; t < NP; t++) {
        ull npx = pk2(-px, -px), npy = pk2(-py, -py), npz = pk2(-pz, -pz);
        float bestv = -1.f; int besti = 0;
        #pragma unroll
        for (int j = 0; j < 4; j++) {
            ull dx = add2(xp[j], npx);              // x - px (exact: a + (-b))
            ull dy = add2(yp[j], npy);
            ull dz = add2(zp[j], npz);
            ull d2 = add2(add2(mul2(dx,dx), mul2(dy,dy)), mul2(dz,dz));
            float d0, d1; upk2(d2, d0, d1);
            int i0 = 2*j, i1 = 2*j + 1;
            dmin[i0] = fminf(dmin[i0], d0);
            if (dmin[i0] > bestv) { bestv = dmin[i0]; besti = base + i0; }
            dmin[i1] = fminf(dmin[i1], d1);
            if (dmin[i1] > bestv) { bestv = dmin[i1]; besti = base + i1; }
        }
        // warp butterfly argmax (ties -> lower index)
        #pragma unroll
        for (int off = 16; off; off >>= 1) {
            float ov = __shfl_xor_sync(0xffffffffu, bestv, off);
            int   oi = __shfl_xor_sync(0xffffffffu, besti, off);
            if (ov > bestv || (ov == bestv && oi < besti)) { bestv = ov; besti = oi; }
        }
        float* rvb = rv + (t & 1)*32;
        int*   rib = ri + (t & 1)*32;
        if (lane == 0) { rvb[wid] = bestv; rib[wid] = besti; }
        __syncthreads();
        // every warp redundantly reduces the 32 warp winners
        bestv = rvb[lane]; besti = rib[lane];
        #pragma unroll
        for (int off = 16; off; off >>= 1) {
            float ov = __shfl_xor_sync(0xffffffffu, bestv, off);
            int   oi = __shfl_xor_sync(0xffffffffu, besti, off);
            if (ov > bestv || (ov == bestv && oi < besti)) { bestv = ov; besti = oi; }
        }
        px = sx[besti]; py = sy[besti]; pz = sz[besti];   // smem broadcast
        if (tid == 0) g_fps[b*NP + t] = besti;
    }
}

// ---------------- gather new_xyz ----------------
__global__ void k_nx(const float* __restrict__ xyz, float* __restrict__ out) {
    int i = blockIdx.x*256 + threadIdx.x;
    int b = i >> 11, q = i & 2047, n = g_fps[i];
    #pragma unroll
    for (int c = 0; c < 3; c++)
        out[((size_t)b*3 + c)*NP + q] = xyz[((size_t)b*3 + c)*NN + n];
}

// ---------------- KNN: warp per query, tiled smem, register top-16 ----------------
__global__ __launch_bounds__(256) void k_knn(const float* __restrict__ xyz) {
    __shared__ float4 s4[2048];                  // 32KB tile
    int b = blockIdx.y, tid = threadIdx.x, lane = tid & 31, w = tid >> 5;
    const float* X = xyz + (size_t)b*3*NN;
    int q = blockIdx.x*8 + w;
    int qi = g_fps[b*NP + q];
    float qx = X[qi], qy = X[NN+qi], qz = X[2*NN+qi];
    float qq = __fadd_rn(__fadd_rn(__fmul_rn(qx,qx), __fmul_rn(qy,qy)), __fmul_rn(qz,qz));

    float bd[KK]; int bi[KK];
    #pragma unroll
    for (int s = 0; s < KK; s++) { bd[s] = 3.0e38f; bi[s] = 0x7fffffff; }
    float wv = 3.0e38f; int ws = 0;

    for (int tile = 0; tile < NN; tile += 2048) {
        __syncthreads();
        for (int j = tid; j < 2048; j += 256) {
            int g = tile + j;
            float xx = X[g], yy = X[NN+g], zz = X[2*NN+g];
            float r = __fadd_rn(__fadd_rn(__fmul_rn(xx,xx), __fmul_rn(yy,yy)), __fmul_rn(zz,zz));
            s4[j] = make_float4(xx, yy, zz, r);
        }
        __syncthreads();
        #pragma unroll 4
        for (int k = 0; k < 2048; k += 32) {
            float4 c = s4[k + lane];
            int j = tile + k + lane;                       // per-lane increasing index
            float dot = __fadd_rn(__fadd_rn(__fmul_rn(qx,c.x), __fmul_rn(qy,c.y)), __fmul_rn(qz,c.z));
            float d = __fsub_rn(__fadd_rn(qq, c.w), __fmul_rn(2.0f, dot));
            if (d < wv) {
                #pragma unroll
                for (int s = 0; s < KK; s++) if (s == ws) { bd[s] = d; bi[s] = j; }
                float nv = -3.0e38f; int ns = 0, ni = -1;
                #pragma unroll
                for (int s = 0; s < KK; s++)
                    if (bd[s] > nv || (bd[s] == nv && bi[s] > ni)) { nv = bd[s]; ns = s; ni = bi[s]; }
                wv = nv; ws = ns;
            }
        }
    }
    // merge 32 lanes' top-16 -> global top-16 (dist asc, ties -> lower index)
    ull key[KK];
    #pragma unroll
    for (int s = 0; s < KK; s++) {
        unsigned u = __float_as_uint(bd[s]);
        u ^= ((unsigned)((int)u >> 31)) | 0x80000000u;   // order-preserving transform
        key[s] = ((ull)u << 32) | (unsigned)bi[s];
    }
    ull mn = key[0]; int ms = 0;
    #pragma unroll
    for (int s = 1; s < KK; s++) if (key[s] < mn) { mn = key[s]; ms = s; }
    int outidx = 0;
    #pragma unroll
    for (int r = 0; r < KK; r++) {
        ull wmin = mn;
        #pragma unroll
        for (int off = 16; off; off >>= 1) {
            ull o = __shfl_xor_sync(0xffffffffu, wmin, off);
            if (o < wmin) wmin = o;
        }
        if (lane == r) outidx = (int)(unsigned)wmin;
        if (wmin == mn) {   // I was the winner: retire the entry, rescan
            #pragma unroll
            for (int s = 0; s < KK; s++) if (s == ms) key[s] = ~0ull;
            mn = key[0]; ms = 0;
            #pragma unroll
            for (int s = 1; s < KK; s++) if (key[s] < mn) { mn = key[s]; ms = s; }
        }
    }
    if (lane < KK) g_knn[((size_t)b*NP + q)*KK + lane] = outidx;
}

// ---------------- Z1 = W1[:,3:] @ points, per point ----------------
__global__ __launch_bounds__(128) void k_z1(const float* __restrict__ pts,
                                            const float* __restrict__ W1) {
    __shared__ float w[FF*FF];
    int tid = threadIdx.x;
    for (int i = tid; i < FF*FF; i += 128) w[i] = W1[(i>>6)*67 + 3 + (i&63)];
    __syncthreads();
    int p = blockIdx.x*128 + tid;
    int b = p >> 13, n = p & (NN-1);
    float xv[FF];
    #pragma unroll
    for (int f = 0; f < FF; f++) xv[f] = pts[((size_t)b*FF + f)*NN + n];
    float* zr = g_Z1 + (size_t)p*FF;
    for (int o = 0; o < FF; o += 4) {
        float a0=0.f, a1=0.f, a2=0.f, a3=0.f;
        #pragma unroll
        for (int f = 0; f < FF; f++) {
            float xf = xv[f];
            a0 = fmaf(w[(o+0)*FF+f], xf, a0);
            a1 = fmaf(w[(o+1)*FF+f], xf, a1);
            a2 = fmaf(w[(o+2)*FF+f], xf, a2);
            a3 = fmaf(w[(o+3)*FF+f], xf, a3);
        }
        *(float4*)(zr + o) = make_float4(a0, a1, a2, a3);
    }
}

// ---------------- pass1: y1 -> g_buf channel-major ----------------
__global__ __launch_bounds__(128) void k_p1(const float* __restrict__ xyz,
                                            const float* __restrict__ W1,
                                            const float* __restrict__ b1,
                                            const float* __restrict__ nxyz) {
    __shared__ float w0[64], w1s[64], w2s[64], bb[64];
    int tid = threadIdx.x;
    if (tid < 64) {
        w0[tid]  = W1[tid*67 + 0]; w1s[tid] = W1[tid*67 + 1];
        w2s[tid] = W1[tid*67 + 2]; bb[tid]  = b1[tid];
    }
    __syncthreads();
    int pos = blockIdx.x*128 + tid;
    int b = pos >> 15, q = (pos >> 4) & 2047, n = g_knn[pos];
    float cx = nxyz[((size_t)b*3+0)*NP+q], cy = nxyz[((size_t)b*3+1)*NP+q], cz = nxyz[((size_t)b*3+2)*NP+q];
    const float* X = xyz + (size_t)b*3*NN;
    float dx = X[n]-cx, dy = X[NN+n]-cy, dz = X[2*NN+n]-cz;
    const float4* zr = (const float4*)(g_Z1 + (size_t)(b*NN + n)*FF);
    #pragma unroll
    for (int i = 0; i < 16; i++) {
        float4 v = zr[i]; int o = 4*i;
        g_buf[(size_t)(o+0)*PP+pos] = fmaf(w2s[o+0],dz, fmaf(w1s[o+0],dy, fmaf(w0[o+0],dx, v.x+bb[o+0])));
        g_buf[(size_t)(o+1)*PP+pos] = fmaf(w2s[o+1],dz, fmaf(w1s[o+1],dy, fmaf(w0[o+1],dx, v.y+bb[o+1])));
        g_buf[(size_t)(o+2)*PP+pos] = fmaf(w2s[o+2],dz, fmaf(w1s[o+2],dy, fmaf(w0[o+2],dx, v.z+bb[o+2])));
        g_buf[(size_t)(o+3)*PP+pos] = fmaf(w2s[o+3],dz, fmaf(w1s[o+3],dy, fmaf(w0[o+3],dx, v.w+bb[o+3])));
    }
}

// ---------------- per-channel sum/sumsq ----------------
__global__ __launch_bounds__(256) void k_st(int which) {
    int o = blockIdx.y;
    const float* src = g_buf + (size_t)o*PP + blockIdx.x*(PP/16);
    float s = 0.f, s2 = 0.f;
    for (int i = threadIdx.x; i < PP/16; i += 256) {
        float v = src[i]; s += v; s2 = fmaf(v, v, s2);
    }
    #pragma unroll
    for (int off = 16; off; off >>= 1) {
        s  += __shfl_down_sync(0xffffffffu, s,  off);
        s2 += __shfl_down_sync(0xffffffffu, s2, off);
    }
    __shared__ float as[8], as2[8];
    int wid = threadIdx.x >> 5;
    if ((threadIdx.x & 31) == 0) { as[wid] = s; as2[wid] = s2; }
    __syncthreads();
    if (threadIdx.x == 0) {
        float ts = 0.f, ts2 = 0.f;
        #pragma unroll
        for (int w = 0; w < 8; w++) { ts += as[w]; ts2 += as2[w]; }
        atomicAdd(g_stats + which*128 + o, ts);
        atomicAdd(g_stats + which*128 + 64 + o, ts2);
    }
}

__global__ void k_fin(const float* __restrict__ gam, const float* __restrict__ bet, int which) {
    int o = threadIdx.x;
    float m = g_stats[which*128 + o] / (float)PP;
    float v = g_stats[which*128 + 64 + o] / (float)PP - m*m;
    v = fmaxf(v, 0.f);
    float sc = gam[o] * rsqrtf(v + 1e-5f);
    g_sc[which*128 + o] = sc;
    g_sc[which*128 + 64 + o] = bet[o] - m*sc;
}

// ---------------- pass2: bn1+relu -> conv2 (in place) ----------------
__global__ __launch_bounds__(128) void k_p2(const float* __restrict__ W2, const float* __restrict__ b2) {
    __shared__ float w[64*64];
    __shared__ float sc[64], sh[64], bb[64];
    int tid = threadIdx.x;
    for (int i = tid; i < 64*64; i += 128) w[i] = W2[i];
    if (tid < 64) { sc[tid] = g_sc[tid]; sh[tid] = g_sc[64+tid]; bb[tid] = b2[tid]; }
    __syncthreads();
    int pos = blockIdx.x*128 + tid;
    float h[64];
    #pragma unroll
    for (int o = 0; o < 64; o++) {
        float y = g_buf[(size_t)o*PP + pos];
        h[o] = fmaxf(fmaf(y, sc[o], sh[o]), 0.f);
    }
    for (int o = 0; o < 64; o++) {
        float a = bb[o];
        const float* wr = w + o*64;
        #pragma unroll
        for (int f = 0; f < 64; f++) a = fmaf(wr[f], h[f], a);
        g_buf[(size_t)o*PP + pos] = a;
    }
}

// ---------------- pass3: bn2+relu -> conv3 -> max over K ----------------
__global__ __launch_bounds__(128) void k_p3(const float* __restrict__ W3, const float* __restrict__ b3,
                                            float* __restrict__ outf) {
    __shared__ float w[128*64];
    __shared__ float sc[64], sh[64], bb[128];
    int tid = threadIdx.x;
    for (int i = tid; i < 128*64; i += 128) w[i] = W3[i];
    if (tid < 64) { sc[tid] = g_sc[128+tid]; sh[tid] = g_sc[192+tid]; }
    if (tid < 128) bb[tid] = b3[tid];
    __syncthreads();
    int pos = blockIdx.x*128 + tid;
    float h[64];
    #pragma unroll
    for (int o = 0; o < 64; o++) {
        float y = g_buf[(size_t)o*PP + pos];
        h[o] = fmaxf(fmaf(y, sc[o], sh[o]), 0.f);
    }
    int lane = tid & 15;
    int q = pos >> 4;
    int b = q >> 11, qq = q & 2047;
    for (int c = 0; c < 4; c++) {
        float acc[32];
        #pragma unroll
        for (int o = 0; o < 32; o++) {
            const float* wr = w + (c*32 + o)*64;
            float a = bb[c*32 + o];
            #pragma unroll
            for (int f = 0; f < 64; f++) a = fmaf(wr[f], h[f], a);
            acc[o] = a;
        }
        #pragma unroll
        for (int o = 0; o < 32; o++) {
            float v = acc[o];
            #pragma unroll
            for (int off = 1; off < 16; off <<= 1)
                v = fmaxf(v, __shfl_xor_sync(0xffffffffu, v, off));
            acc[o] = v;
        }
        #pragma unroll
        for (int o = 0; o < 32; o++)
            if ((o & 15) == lane)
                outf[((size_t)b*128 + c*32 + o)*NP + qq] = acc[o];
    }
}

extern "C" void kernel_launch(void* const* d_in, const int* in_sizes, int n_in,
                              void* d_out, int out_size) {
    const float* xyz = (const float*)d_in[0];
    const float* pts = (const float*)d_in[1];
    const float* W1  = (const float*)d_in[2];
    const float* b1  = (const float*)d_in[3];
    const float* g1  = (const float*)d_in[4];
    const float* be1 = (const float*)d_in[5];
    const float* W2  = (const float*)d_in[6];
    const float* b2  = (const float*)d_in[7];
    const float* g2  = (const float*)d_in[8];
    const float* be2 = (const float*)d_in[9];
    const float* W3  = (const float*)d_in[10];
    const float* b3  = (const float*)d_in[11];
    float* out  = (float*)d_out;
    float* onx  = out;                       // new_xyz (B,3,NP)
    float* ofe  = out + (size_t)BB*3*NP;     // new_feat (B,128,NP)

    const int FPS_SM = (3*NN + 128)*4;
    cudaFuncSetAttribute(k_fps, cudaFuncAttributeMaxDynamicSharedMemorySize, FPS_SM);

    k_zero<<<1, 256>>>();
    k_fps<<<BB, 1024, FPS_SM>>>(xyz);
    k_nx<<<(BB*NP)/256, 256>>>(xyz, onx);
    k_knn<<<dim3(NP/8, BB), 256>>>(xyz);
    k_z1<<<PTSN/128, 128>>>(pts, W1);
    k_p1<<<PP/128, 128>>>(xyz, W1, b1, onx);
    k_st<<<dim3(16, 64), 256>>>(0);
    k_fin<<<1, 64>>>(g1, be1, 0);
    k_p2<<<PP/128, 128>>>(W2, b2);
    k_st<<<dim3(16, 64), 256>>>(1);
    k_fin<<<1, 64>>>(g2, be2, 1);
    k_p3<<<PP/128, 128>>>(W3, b3, ofe);
}

// round 4
// speedup vs baseline: 1.3810x; 1.3259x over previous
#include <cuda_runtime.h>

#define BB 8
#define NN 8192
#define NP 2048
#define KK 16
#define FF 64
#define PP (BB*NP*KK)
#define PTSN (BB*NN)

typedef unsigned long long ull;

__device__ float g_Z1[(size_t)PTSN*FF];
__device__ float g_buf[(size_t)PP*FF];
__device__ int   g_fps[BB*NP];
__device__ int   g_knn[PP];
__device__ float g_stats[256];
__device__ float g_sc[256];

__global__ void k_zero() { g_stats[threadIdx.x] = 0.f; }

// ---- packed f32x2 helpers (per-lane IEEE rn, identical to scalar) ----
__device__ __forceinline__ ull pk2(float lo, float hi) {
    ull r; asm("mov.b64 %0, {%1,%2};" : "=l"(r) : "f"(lo), "f"(hi)); return r;
}
__device__ __forceinline__ void upk2(ull v, float& lo, float& hi) {
    asm("mov.b64 {%0,%1}, %2;" : "=f"(lo), "=f"(hi) : "l"(v));
}
__device__ __forceinline__ ull add2(ull a, ull b) {
    ull r; asm("add.rn.f32x2 %0, %1, %2;" : "=l"(r) : "l"(a), "l"(b)); return r;
}
__device__ __forceinline__ ull mul2(ull a, ull b) {
    ull r; asm("mul.rn.f32x2 %0, %1, %2;" : "=l"(r) : "l"(a), "l"(b)); return r;
}

// ---------------- FPS: one block per batch, 512 thr x 16 pts ----------------
__global__ __launch_bounds__(512) void k_fps(const float* __restrict__ xyz) {
    extern __shared__ float sm[];
    float* sx = sm; float* sy = sm + NN; float* sz = sm + 2*NN;
    float* rv = sm + 3*NN;            // 32 floats (double-buffered 2x16)
    int*   ri = (int*)(rv + 32);      // 32 ints

    int b = blockIdx.x, tid = threadIdx.x, lane = tid & 31, wid = tid >> 5;
    int base = tid*16;
    const float* X = xyz + (size_t)b*3*NN;

    ull xp[8], yp[8], zp[8];
    float dmin[16];
    #pragma unroll
    for (int i = 0; i < 16; i += 4) {
        float4 vx = *(const float4*)(X + base + i);
        float4 vy = *(const float4*)(X + NN + base + i);
        float4 vz = *(const float4*)(X + 2*NN + base + i);
        xp[i/2]   = pk2(vx.x, vx.y); xp[i/2+1] = pk2(vx.z, vx.w);
        yp[i/2]   = pk2(vy.x, vy.y); yp[i/2+1] = pk2(vy.z, vy.w);
        zp[i/2]   = pk2(vz.x, vz.y); zp[i/2+1] = pk2(vz.z, vz.w);
        sx[base+i]=vx.x; sx[base+i+1]=vx.y; sx[base+i+2]=vx.z; sx[base+i+3]=vx.w;
        sy[base+i]=vy.x; sy[base+i+1]=vy.y; sy[base+i+2]=vy.z; sy[base+i+3]=vy.w;
        sz[base+i]=vz.x; sz[base+i+1]=vz.y; sz[base+i+2]=vz.z; sz[base+i+3]=vz.w;
    }
    #pragma unroll
    for (int i = 0; i < 16; i++) dmin[i] = 1e10f;

    float px = X[0], py = X[NN], pz = X[2*NN];
    if (tid == 0) g_fps[b*NP] = 0;
    __syncthreads();

    for (int t = 1; t < NP; t++) {
        ull npx = pk2(-px, -px), npy = pk2(-py, -py), npz = pk2(-pz, -pz);
        float bestv = -1.f; int besti = 0;
        #pragma unroll
        for (int j = 0; j < 8; j++) {
            ull dx = add2(xp[j], npx);
            ull dy = add2(yp[j], npy);
            ull dz = add2(zp[j], npz);
            ull d2 = add2(add2(mul2(dx,dx), mul2(dy,dy)), mul2(dz,dz));
            float d0, d1; upk2(d2, d0, d1);
            int i0 = 2*j, i1 = 2*j + 1;
            dmin[i0] = fminf(dmin[i0], d0);
            if (dmin[i0] > bestv) { bestv = dmin[i0]; besti = base + i0; }
            dmin[i1] = fminf(dmin[i1], d1);
            if (dmin[i1] > bestv) { bestv = dmin[i1]; besti = base + i1; }
        }
        // warp butterfly argmax (ties -> lower index)
        #pragma unroll
        for (int off = 16; off; off >>= 1) {
            float ov = __shfl_xor_sync(0xffffffffu, bestv, off);
            int   oi = __shfl_xor_sync(0xffffffffu, besti, off);
            if (ov > bestv || (ov == bestv && oi < besti)) { bestv = ov; besti = oi; }
        }
        float* rvb = rv + (t & 1)*16;
        int*   rib = ri + (t & 1)*16;
        if (lane == 0) { rvb[wid] = bestv; rib[wid] = besti; }
        __syncthreads();
        // every warp redundantly reduces the 16 warp winners (entries duplicated via lane&15)
        bestv = rvb[lane & 15]; besti = rib[lane & 15];
        #pragma unroll
        for (int off = 8; off; off >>= 1) {
            float ov = __shfl_xor_sync(0xffffffffu, bestv, off);
            int   oi = __shfl_xor_sync(0xffffffffu, besti, off);
            if (ov > bestv || (ov == bestv && oi < besti)) { bestv = ov; besti = oi; }
        }
        px = sx[besti]; py = sy[besti]; pz = sz[besti];
        if (tid == 0) g_fps[b*NP + t] = besti;
    }
}

// ---------------- gather new_xyz ----------------
__global__ void k_nx(const float* __restrict__ xyz, float* __restrict__ out) {
    int i = blockIdx.x*256 + threadIdx.x;
    int b = i >> 11, q = i & 2047, n = g_fps[i];
    #pragma unroll
    for (int c = 0; c < 3; c++)
        out[((size_t)b*3 + c)*NP + q] = xyz[((size_t)b*3 + c)*NN + n];
}

// ---------------- KNN: warp-cooperative top-32, ballot-serialized inserts ----------------
__global__ __launch_bounds__(256) void k_knn(const float* __restrict__ xyz) {
    __shared__ float4 s4[2048];
    int b = blockIdx.y, tid = threadIdx.x, lane = tid & 31, w = tid >> 5;
    const float* X = xyz + (size_t)b*3*NN;
    int q = blockIdx.x*8 + w;
    int qi = g_fps[b*NP + q];
    float qx = X[qi], qy = X[NN+qi], qz = X[2*NN+qi];
    float qq = __fadd_rn(__fadd_rn(__fmul_rn(qx,qx), __fmul_rn(qy,qy)), __fmul_rn(qz,qz));

    ull held = ~0ull;          // this lane's held key (empty = max)
    ull wmax = ~0ull;          // current max over warp's 32 held keys
    int wlane = 0;             // lane holding wmax

    for (int tile = 0; tile < NN; tile += 2048) {
        __syncthreads();
        for (int j = tid; j < 2048; j += 256) {
            int g = tile + j;
            float xx = X[g], yy = X[NN+g], zz = X[2*NN+g];
            float r = __fadd_rn(__fadd_rn(__fmul_rn(xx,xx), __fmul_rn(yy,yy)), __fmul_rn(zz,zz));
            s4[j] = make_float4(xx, yy, zz, r);
        }
        __syncthreads();
        for (int k = 0; k < 2048; k += 32) {
            float4 c = s4[k + lane];
            int j = tile + k + lane;
            float dot = __fadd_rn(__fadd_rn(__fmul_rn(qx,c.x), __fmul_rn(qy,c.y)), __fmul_rn(qz,c.z));
            float d = __fsub_rn(__fadd_rn(qq, c.w), __fmul_rn(2.0f, dot));
            unsigned u = __float_as_uint(d);
            u ^= ((unsigned)((int)u >> 31)) | 0x80000000u;    // order-preserving
            ull key = ((ull)u << 32) | (unsigned)j;
            unsigned m = __ballot_sync(0xffffffffu, key < wmax);
            while (m) {
                int src = __ffs(m) - 1; m &= m - 1;
                ull k2 = __shfl_sync(0xffffffffu, key, src);
                if (k2 < wmax) {                   // recheck: wmax shrank
                    if (lane == wlane) held = k2;  // replace current max holder
                    ull v = held; int l = lane;    // recompute (wmax, wlane)
                    #pragma unroll
                    for (int off = 16; off; off >>= 1) {
                        ull ov = __shfl_xor_sync(0xffffffffu, v, off);
                        int  ol = __shfl_xor_sync(0xffffffffu, l, off);
                        if (ov > v || (ov == v && ol < l)) { v = ov; l = ol; }
                    }
                    wmax = v; wlane = l;
                }
            }
        }
    }
    // extract the 16 smallest keys in ascending order
    int outidx = 0;
    #pragma unroll
    for (int r = 0; r < KK; r++) {
        ull v = held;
        #pragma unroll
        for (int off = 16; off; off >>= 1) {
            ull ov = __shfl_xor_sync(0xffffffffu, v, off);
            if (ov < v) v = ov;
        }
        if (lane == r) outidx = (int)(unsigned)v;
        if (held == v) held = ~0ull;               // unique winner retires
    }
    if (lane < KK) g_knn[((size_t)b*NP + q)*KK + lane] = outidx;
}

// ---------------- Z1 = W1[:,3:] @ points, per point ----------------
__global__ __launch_bounds__(128) void k_z1(const float* __restrict__ pts,
                                            const float* __restrict__ W1) {
    __shared__ float w[FF*FF];
    int tid = threadIdx.x;
    for (int i = tid; i < FF*FF; i += 128) w[i] = W1[(i>>6)*67 + 3 + (i&63)];
    __syncthreads();
    int p = blockIdx.x*128 + tid;
    int b = p >> 13, n = p & (NN-1);
    float xv[FF];
    #pragma unroll
    for (int f = 0; f < FF; f++) xv[f] = pts[((size_t)b*FF + f)*NN + n];
    float* zr = g_Z1 + (size_t)p*FF;
    for (int o = 0; o < FF; o += 4) {
        float a0=0.f, a1=0.f, a2=0.f, a3=0.f;
        #pragma unroll
        for (int f = 0; f < FF; f++) {
            float xf = xv[f];
            a0 = fmaf(w[(o+0)*FF+f], xf, a0);
            a1 = fmaf(w[(o+1)*FF+f], xf, a1);
            a2 = fmaf(w[(o+2)*FF+f], xf, a2);
            a3 = fmaf(w[(o+3)*FF+f], xf, a3);
        }
        *(float4*)(zr + o) = make_float4(a0, a1, a2, a3);
    }
}

// ---------------- pass1: y1 -> g_buf channel-major ----------------
__global__ __launch_bounds__(128) void k_p1(const float* __restrict__ xyz,
                                            const float* __restrict__ W1,
                                            const float* __restrict__ b1,
                                            const float* __restrict__ nxyz) {
    __shared__ float w0[64], w1s[64], w2s[64], bb[64];
    int tid = threadIdx.x;
    if (tid < 64) {
        w0[tid]  = W1[tid*67 + 0]; w1s[tid] = W1[tid*67 + 1];
        w2s[tid] = W1[tid*67 + 2]; bb[tid]  = b1[tid];
    }
    __syncthreads();
    int pos = blockIdx.x*128 + tid;
    int b = pos >> 15, q = (pos >> 4) & 2047, n = g_knn[pos];
    float cx = nxyz[((size_t)b*3+0)*NP+q], cy = nxyz[((size_t)b*3+1)*NP+q], cz = nxyz[((size_t)b*3+2)*NP+q];
    const float* X = xyz + (size_t)b*3*NN;
    float dx = X[n]-cx, dy = X[NN+n]-cy, dz = X[2*NN+n]-cz;
    const float4* zr = (const float4*)(g_Z1 + (size_t)(b*NN + n)*FF);
    #pragma unroll
    for (int i = 0; i < 16; i++) {
        float4 v = zr[i]; int o = 4*i;
        g_buf[(size_t)(o+0)*PP+pos] = fmaf(w2s[o+0],dz, fmaf(w1s[o+0],dy, fmaf(w0[o+0],dx, v.x+bb[o+0])));
        g_buf[(size_t)(o+1)*PP+pos] = fmaf(w2s[o+1],dz, fmaf(w1s[o+1],dy, fmaf(w0[o+1],dx, v.y+bb[o+1])));
        g_buf[(size_t)(o+2)*PP+pos] = fmaf(w2s[o+2],dz, fmaf(w1s[o+2],dy, fmaf(w0[o+2],dx, v.z+bb[o+2])));
        g_buf[(size_t)(o+3)*PP+pos] = fmaf(w2s[o+3],dz, fmaf(w1s[o+3],dy, fmaf(w0[o+3],dx, v.w+bb[o+3])));
    }
}

// ---------------- per-channel sum/sumsq ----------------
__global__ __launch_bounds__(256) void k_st(int which) {
    int o = blockIdx.y;
    const float* src = g_buf + (size_t)o*PP + blockIdx.x*(PP/16);
    float s = 0.f, s2 = 0.f;
    for (int i = threadIdx.x; i < PP/16; i += 256) {
        float v = src[i]; s += v; s2 = fmaf(v, v, s2);
    }
    #pragma unroll
    for (int off = 16; off; off >>= 1) {
        s  += __shfl_down_sync(0xffffffffu, s,  off);
        s2 += __shfl_down_sync(0xffffffffu, s2, off);
    }
    __shared__ float as[8], as2[8];
    int wid = threadIdx.x >> 5;
    if ((threadIdx.x & 31) == 0) { as[wid] = s; as2[wid] = s2; }
    __syncthreads();
    if (threadIdx.x == 0) {
        float ts = 0.f, ts2 = 0.f;
        #pragma unroll
        for (int w = 0; w < 8; w++) { ts += as[w]; ts2 += as2[w]; }
        atomicAdd(g_stats + which*128 + o, ts);
        atomicAdd(g_stats + which*128 + 64 + o, ts2);
    }
}

__global__ void k_fin(const float* __restrict__ gam, const float* __restrict__ bet, int which) {
    int o = threadIdx.x;
    float m = g_stats[which*128 + o] / (float)PP;
    float v = g_stats[which*128 + 64 + o] / (float)PP - m*m;
    v = fmaxf(v, 0.f);
    float sc = gam[o] * rsqrtf(v + 1e-5f);
    g_sc[which*128 + o] = sc;
    g_sc[which*128 + 64 + o] = bet[o] - m*sc;
}

// ---------------- pass2: bn1+relu -> conv2 (in place) ----------------
__global__ __launch_bounds__(128) void k_p2(const float* __restrict__ W2, const float* __restrict__ b2) {
    __shared__ float w[64*64];
    __shared__ float sc[64], sh[64], bb[64];
    int tid = threadIdx.x;
    for (int i = tid; i < 64*64; i += 128) w[i] = W2[i];
    if (tid < 64) { sc[tid] = g_sc[tid]; sh[tid] = g_sc[64+tid]; bb[tid] = b2[tid]; }
    __syncthreads();
    int pos = blockIdx.x*128 + tid;
    float h[64];
    #pragma unroll
    for (int o = 0; o < 64; o++) {
        float y = g_buf[(size_t)o*PP + pos];
        h[o] = fmaxf(fmaf(y, sc[o], sh[o]), 0.f);
    }
    for (int o = 0; o < 64; o++) {
        float a = bb[o];
        const float* wr = w + o*64;
        #pragma unroll
        for (int f = 0; f < 64; f++) a = fmaf(wr[f], h[f], a);
        g_buf[(size_t)o*PP + pos] = a;
    }
}

// ---------------- pass3: bn2+relu -> conv3 -> max over K ----------------
__global__ __launch_bounds__(128) void k_p3(const float* __restrict__ W3, const float* __restrict__ b3,
                                            float* __restrict__ outf) {
    __shared__ float w[128*64];
    __shared__ float sc[64], sh[64], bb[128];
    int tid = threadIdx.x;
    for (int i = tid; i < 128*64; i += 128) w[i] = W3[i];
    if (tid < 64) { sc[tid] = g_sc[128+tid]; sh[tid] = g_sc[192+tid]; }
    if (tid < 128) bb[tid] = b3[tid];
    __syncthreads();
    int pos = blockIdx.x*128 + tid;
    float h[64];
    #pragma unroll
    for (int o = 0; o < 64; o++) {
        float y = g_buf[(size_t)o*PP + pos];
        h[o] = fmaxf(fmaf(y, sc[o], sh[o]), 0.f);
    }
    int lane = tid & 15;
    int q = pos >> 4;
    int b = q >> 11, qq = q & 2047;
    for (int c = 0; c < 4; c++) {
        float acc[32];
        #pragma unroll
        for (int o = 0; o < 32; o++) {
            const float* wr = w + (c*32 + o)*64;
            float a = bb[c*32 + o];
            #pragma unroll
            for (int f = 0; f < 64; f++) a = fmaf(wr[f], h[f], a);
            acc[o] = a;
        }
        #pragma unroll
        for (int o = 0; o < 32; o++) {
            float v = acc[o];
            #pragma unroll
            for (int off = 1; off < 16; off <<= 1)
                v = fmaxf(v, __shfl_xor_sync(0xffffffffu, v, off));
            acc[o] = v;
        }
        #pragma unroll
        for (int o = 0; o < 32; o++)
            if ((o & 15) == lane)
                outf[((size_t)b*128 + c*32 + o)*NP + qq] = acc[o];
    }
}

extern "C" void kernel_launch(void* const* d_in, const int* in_sizes, int n_in,
                              void* d_out, int out_size) {
    const float* xyz = (const float*)d_in[0];
    const float* pts = (const float*)d_in[1];
    const float* W1  = (const float*)d_in[2];
    const float* b1  = (const float*)d_in[3];
    const float* g1  = (const float*)d_in[4];
    const float* be1 = (const float*)d_in[5];
    const float* W2  = (const float*)d_in[6];
    const float* b2  = (const float*)d_in[7];
    const float* g2  = (const float*)d_in[8];
    const float* be2 = (const float*)d_in[9];
    const float* W3  = (const float*)d_in[10];
    const float* b3  = (const float*)d_in[11];
    float* out  = (float*)d_out;
    float* onx  = out;
    float* ofe  = out + (size_t)BB*3*NP;

    const int FPS_SM = (3*NN + 64)*4;
    cudaFuncSetAttribute(k_fps, cudaFuncAttributeMaxDynamicSharedMemorySize, FPS_SM);

    k_zero<<<1, 256>>>();
    k_fps<<<BB, 512, FPS_SM>>>(xyz);
    k_nx<<<(BB*NP)/256, 256>>>(xyz, onx);
    k_knn<<<dim3(NP/8, BB), 256>>>(xyz);
    k_z1<<<PTSN/128, 128>>>(pts, W1);
    k_p1<<<PP/128, 128>>>(xyz, W1, b1, onx);
    k_st<<<dim3(16, 64), 256>>>(0);
    k_fin<<<1, 64>>>(g1, be1, 0);
    k_p2<<<PP/128, 128>>>(W2, b2);
    k_st<<<dim3(16, 64), 256>>>(1);
    k_fin<<<1, 64>>>(g2, be2, 1);
    k_p3<<<PP/128, 128>>>(W3, b3, ofe);
}

// round 5
// speedup vs baseline: 1.3825x; 1.0011x over previous
#include <cuda_runtime.h>

#define BB 8
#define NN 8192
#define NP 2048
#define KK 16
#define FF 64
#define PP (BB*NP*KK)
#define PTSN (BB*NN)

typedef unsigned long long ull;

__device__ float g_Z1[(size_t)PTSN*FF];
__device__ float g_buf[(size_t)PP*FF];
__device__ int   g_fps[BB*NP];
__device__ int   g_knn[PP];
__device__ float g_stats[256];
__device__ float g_sc[256];

__global__ void k_zero() { g_stats[threadIdx.x] = 0.f; }

// ---- packed f32x2 helpers (per-lane IEEE rn, identical to scalar) ----
__device__ __forceinline__ ull pk2(float lo, float hi) {
    ull r; asm("mov.b64 %0, {%1,%2};" : "=l"(r) : "f"(lo), "f"(hi)); return r;
}
__device__ __forceinline__ void upk2(ull v, float& lo, float& hi) {
    asm("mov.b64 {%0,%1}, %2;" : "=f"(lo), "=f"(hi) : "l"(v));
}
__device__ __forceinline__ ull add2(ull a, ull b) {
    ull r; asm("add.rn.f32x2 %0, %1, %2;" : "=l"(r) : "l"(a), "l"(b)); return r;
}
__device__ __forceinline__ ull mul2(ull a, ull b) {
    ull r; asm("mul.rn.f32x2 %0, %1, %2;" : "=l"(r) : "l"(a), "l"(b)); return r;
}

// ---------------- FPS: one block per batch, 512 thr x 16 pts ----------------
__global__ __launch_bounds__(512) void k_fps(const float* __restrict__ xyz) {
    extern __shared__ float sm[];
    float* sx = sm; float* sy = sm + NN; float* sz = sm + 2*NN;
    float* rv = sm + 3*NN;            // 32 floats (double-buffered 2x16)
    int*   ri = (int*)(rv + 32);      // 32 ints

    int b = blockIdx.x, tid = threadIdx.x, lane = tid & 31, wid = tid >> 5;
    int base = tid*16;
    const float* X = xyz + (size_t)b*3*NN;

    ull xp[8], yp[8], zp[8];
    float dmin[16];
    #pragma unroll
    for (int i = 0; i < 16; i += 4) {
        float4 vx = *(const float4*)(X + base + i);
        float4 vy = *(const float4*)(X + NN + base + i);
        float4 vz = *(const float4*)(X + 2*NN + base + i);
        xp[i/2]   = pk2(vx.x, vx.y); xp[i/2+1] = pk2(vx.z, vx.w);
        yp[i/2]   = pk2(vy.x, vy.y); yp[i/2+1] = pk2(vy.z, vy.w);
        zp[i/2]   = pk2(vz.x, vz.y); zp[i/2+1] = pk2(vz.z, vz.w);
        sx[base+i]=vx.x; sx[base+i+1]=vx.y; sx[base+i+2]=vx.z; sx[base+i+3]=vx.w;
        sy[base+i]=vy.x; sy[base+i+1]=vy.y; sy[base+i+2]=vy.z; sy[base+i+3]=vy.w;
        sz[base+i]=vz.x; sz[base+i+1]=vz.y; sz[base+i+2]=vz.z; sz[base+i+3]=vz.w;
    }
    #pragma unroll
    for (int i = 0; i < 16; i++) dmin[i] = 1e10f;

    float px = X[0], py = X[NN], pz = X[2*NN];
    if (tid == 0) g_fps[b*NP] = 0;
    __syncthreads();

    for (int t = 1; t < NP; t++) {
        ull npx = pk2(-px, -px), npy = pk2(-py, -py), npz = pk2(-pz, -pz);
        float bestv = -1.f; int besti = 0;
        #pragma unroll
        for (int j = 0; j < 8; j++) {
            ull dx = add2(xp[j], npx);
            ull dy = add2(yp[j], npy);
            ull dz = add2(zp[j], npz);
            ull d2 = add2(add2(mul2(dx,dx), mul2(dy,dy)), mul2(dz,dz));
            float d0, d1; upk2(d2, d0, d1);
            int i0 = 2*j, i1 = 2*j + 1;
            dmin[i0] = fminf(dmin[i0], d0);
            if (dmin[i0] > bestv) { bestv = dmin[i0]; besti = base + i0; }
            dmin[i1] = fminf(dmin[i1], d1);
            if (dmin[i1] > bestv) { bestv = dmin[i1]; besti = base + i1; }
        }
        // warp butterfly argmax (ties -> lower index)
        #pragma unroll
        for (int off = 16; off; off >>= 1) {
            float ov = __shfl_xor_sync(0xffffffffu, bestv, off);
            int   oi = __shfl_xor_sync(0xffffffffu, besti, off);
            if (ov > bestv || (ov == bestv && oi < besti)) { bestv = ov; besti = oi; }
        }
        float* rvb = rv + (t & 1)*16;
        int*   rib = ri + (t & 1)*16;
        if (lane == 0) { rvb[wid] = bestv; rib[wid] = besti; }
        __syncthreads();
        // every warp redundantly reduces the 16 warp winners (entries duplicated via lane&15)
        bestv = rvb[lane & 15]; besti = rib[lane & 15];
        #pragma unroll
        for (int off = 8; off; off >>= 1) {
            float ov = __shfl_xor_sync(0xffffffffu, bestv, off);
            int   oi = __shfl_xor_sync(0xffffffffu, besti, off);
            if (ov > bestv || (ov == bestv && oi < besti)) { bestv = ov; besti = oi; }
        }
        px = sx[besti]; py = sy[besti]; pz = sz[besti];
        if (tid == 0) g_fps[b*NP + t] = besti;
    }
}

// ---------------- gather new_xyz ----------------
__global__ void k_nx(const float* __restrict__ xyz, float* __restrict__ out) {
    int i = blockIdx.x*256 + threadIdx.x;
    int b = i >> 11, q = i & 2047, n = g_fps[i];
    #pragma unroll
    for (int c = 0; c < 3; c++)
        out[((size_t)b*3 + c)*NP + q] = xyz[((size_t)b*3 + c)*NN + n];
}

// ---------------- KNN: warp-cooperative top-32, ballot-serialized inserts ----------------
__global__ __launch_bounds__(256) void k_knn(const float* __restrict__ xyz) {
    __shared__ float4 s4[2048];
    int b = blockIdx.y, tid = threadIdx.x, lane = tid & 31, w = tid >> 5;
    const float* X = xyz + (size_t)b*3*NN;
    int q = blockIdx.x*8 + w;
    int qi = g_fps[b*NP + q];
    float qx = X[qi], qy = X[NN+qi], qz = X[2*NN+qi];
    float qq = __fadd_rn(__fadd_rn(__fmul_rn(qx,qx), __fmul_rn(qy,qy)), __fmul_rn(qz,qz));

    ull held = ~0ull;          // this lane's held key (empty = max)
    ull wmax = ~0ull;          // current max over warp's 32 held keys
    int wlane = 0;             // lane holding wmax

    for (int tile = 0; tile < NN; tile += 2048) {
        __syncthreads();
        for (int j = tid; j < 2048; j += 256) {
            int g = tile + j;
            float xx = X[g], yy = X[NN+g], zz = X[2*NN+g];
            float r = __fadd_rn(__fadd_rn(__fmul_rn(xx,xx), __fmul_rn(yy,yy)), __fmul_rn(zz,zz));
            s4[j] = make_float4(xx, yy, zz, r);
        }
        __syncthreads();
        for (int k = 0; k < 2048; k += 32) {
            float4 c = s4[k + lane];
            int j = tile + k + lane;
            float dot = __fadd_rn(__fadd_rn(__fmul_rn(qx,c.x), __fmul_rn(qy,c.y)), __fmul_rn(qz,c.z));
            float d = __fsub_rn(__fadd_rn(qq, c.w), __fmul_rn(2.0f, dot));
            unsigned u = __float_as_uint(d);
            u ^= ((unsigned)((int)u >> 31)) | 0x80000000u;    // order-preserving
            ull key = ((ull)u << 32) | (unsigned)j;
            unsigned m = __ballot_sync(0xffffffffu, key < wmax);
            while (m) {
                int src = __ffs(m) - 1; m &= m - 1;
                ull k2 = __shfl_sync(0xffffffffu, key, src);
                if (k2 < wmax) {                   // recheck: wmax shrank
                    if (lane == wlane) held = k2;  // replace current max holder
                    ull v = held; int l = lane;    // recompute (wmax, wlane)
                    #pragma unroll
                    for (int off = 16; off; off >>= 1) {
                        ull ov = __shfl_xor_sync(0xffffffffu, v, off);
                        int  ol = __shfl_xor_sync(0xffffffffu, l, off);
                        if (ov > v || (ov == v && ol < l)) { v = ov; l = ol; }
                    }
                    wmax = v; wlane = l;
                }
            }
        }
    }
    // extract the 16 smallest keys in ascending order
    int outidx = 0;
    #pragma unroll
    for (int r = 0; r < KK; r++) {
        ull v = held;
        #pragma unroll
        for (int off = 16; off; off >>= 1) {
            ull ov = __shfl_xor_sync(0xffffffffu, v, off);
            if (ov < v) v = ov;
        }
        if (lane == r) outidx = (int)(unsigned)v;
        if (held == v) held = ~0ull;               // unique winner retires
    }
    if (lane < KK) g_knn[((size_t)b*NP + q)*KK + lane] = outidx;
}

// ---------------- Z1 = W1[:,3:] @ points, per point ----------------
__global__ __launch_bounds__(128) void k_z1(const float* __restrict__ pts,
                                            const float* __restrict__ W1) {
    __shared__ float w[FF*FF];
    int tid = threadIdx.x;
    for (int i = tid; i < FF*FF; i += 128) w[i] = W1[(i>>6)*67 + 3 + (i&63)];
    __syncthreads();
    int p = blockIdx.x*128 + tid;
    int b = p >> 13, n = p & (NN-1);
    float xv[FF];
    #pragma unroll
    for (int f = 0; f < FF; f++) xv[f] = pts[((size_t)b*FF + f)*NN + n];
    float* zr = g_Z1 + (size_t)p*FF;
    for (int o = 0; o < FF; o += 4) {
        float a0=0.f, a1=0.f, a2=0.f, a3=0.f;
        #pragma unroll
        for (int f = 0; f < FF; f++) {
            float xf = xv[f];
            a0 = fmaf(w[(o+0)*FF+f], xf, a0);
            a1 = fmaf(w[(o+1)*FF+f], xf, a1);
            a2 = fmaf(w[(o+2)*FF+f], xf, a2);
            a3 = fmaf(w[(o+3)*FF+f], xf, a3);
        }
        *(float4*)(zr + o) = make_float4(a0, a1, a2, a3);
    }
}

// ---------------- pass1: y1 -> g_buf channel-major ----------------
__global__ __launch_bounds__(128) void k_p1(const float* __restrict__ xyz,
                                            const float* __restrict__ W1,
                                            const float* __restrict__ b1,
                                            const float* __restrict__ nxyz) {
    __shared__ float w0[64], w1s[64], w2s[64], bb[64];
    int tid = threadIdx.x;
    if (tid < 64) {
        w0[tid]  = W1[tid*67 + 0]; w1s[tid] = W1[tid*67 + 1];
        w2s[tid] = W1[tid*67 + 2]; bb[tid]  = b1[tid];
    }
    __syncthreads();
    int pos = blockIdx.x*128 + tid;
    int b = pos >> 15, q = (pos >> 4) & 2047, n = g_knn[pos];
    float cx = nxyz[((size_t)b*3+0)*NP+q], cy = nxyz[((size_t)b*3+1)*NP+q], cz = nxyz[((size_t)b*3+2)*NP+q];
    const float* X = xyz + (size_t)b*3*NN;
    float dx = X[n]-cx, dy = X[NN+n]-cy, dz = X[2*NN+n]-cz;
    const float4* zr = (const float4*)(g_Z1 + (size_t)(b*NN + n)*FF);
    #pragma unroll
    for (int i = 0; i < 16; i++) {
        float4 v = zr[i]; int o = 4*i;
        g_buf[(size_t)(o+0)*PP+pos] = fmaf(w2s[o+0],dz, fmaf(w1s[o+0],dy, fmaf(w0[o+0],dx, v.x+bb[o+0])));
        g_buf[(size_t)(o+1)*PP+pos] = fmaf(w2s[o+1],dz, fmaf(w1s[o+1],dy, fmaf(w0[o+1],dx, v.y+bb[o+1])));
        g_buf[(size_t)(o+2)*PP+pos] = fmaf(w2s[o+2],dz, fmaf(w1s[o+2],dy, fmaf(w0[o+2],dx, v.z+bb[o+2])));
        g_buf[(size_t)(o+3)*PP+pos] = fmaf(w2s[o+3],dz, fmaf(w1s[o+3],dy, fmaf(w0[o+3],dx, v.w+bb[o+3])));
    }
}

// ---------------- per-channel sum/sumsq ----------------
__global__ __launch_bounds__(256) void k_st(int which) {
    int o = blockIdx.y;
    const float* src = g_buf + (size_t)o*PP + blockIdx.x*(PP/16);
    float s = 0.f, s2 = 0.f;
    for (int i = threadIdx.x; i < PP/16; i += 256) {
        float v = src[i]; s += v; s2 = fmaf(v, v, s2);
    }
    #pragma unroll
    for (int off = 16; off; off >>= 1) {
        s  += __shfl_down_sync(0xffffffffu, s,  off);
        s2 += __shfl_down_sync(0xffffffffu, s2, off);
    }
    __shared__ float as[8], as2[8];
    int wid = threadIdx.x >> 5;
    if ((threadIdx.x & 31) == 0) { as[wid] = s; as2[wid] = s2; }
    __syncthreads();
    if (threadIdx.x == 0) {
        float ts = 0.f, ts2 = 0.f;
        #pragma unroll
        for (int w = 0; w < 8; w++) { ts += as[w]; ts2 += as2[w]; }
        atomicAdd(g_stats + which*128 + o, ts);
        atomicAdd(g_stats + which*128 + 64 + o, ts2);
    }
}

__global__ void k_fin(const float* __restrict__ gam, const float* __restrict__ bet, int which) {
    int o = threadIdx.x;
    float m = g_stats[which*128 + o] / (float)PP;
    float v = g_stats[which*128 + 64 + o] / (float)PP - m*m;
    v = fmaxf(v, 0.f);
    float sc = gam[o] * rsqrtf(v + 1e-5f);
    g_sc[which*128 + o] = sc;
    g_sc[which*128 + 64 + o] = bet[o] - m*sc;
}

// ---------------- pass2: bn1+relu -> conv2 (in place) ----------------
__global__ __launch_bounds__(128) void k_p2(const float* __restrict__ W2, const float* __restrict__ b2) {
    __shared__ float w[64*64];
    __shared__ float sc[64], sh[64], bb[64];
    int tid = threadIdx.x;
    for (int i = tid; i < 64*64; i += 128) w[i] = W2[i];
    if (tid < 64) { sc[tid] = g_sc[tid]; sh[tid] = g_sc[64+tid]; bb[tid] = b2[tid]; }
    __syncthreads();
    int pos = blockIdx.x*128 + tid;
    float h[64];
    #pragma unroll
    for (int o = 0; o < 64; o++) {
        float y = g_buf[(size_t)o*PP + pos];
        h[o] = fmaxf(fmaf(y, sc[o], sh[o]), 0.f);
    }
    for (int o = 0; o < 64; o++) {
        float a = bb[o];
        const float* wr = w + o*64;
        #pragma unroll
        for (int f = 0; f < 64; f++) a = fmaf(wr[f], h[f], a);
        g_buf[(size_t)o*PP + pos] = a;
    }
}

// ---------------- pass3: bn2+relu -> conv3 -> max over K ----------------
__global__ __launch_bounds__(128) void k_p3(const float* __restrict__ W3, const float* __restrict__ b3,
                                            float* __restrict__ outf) {
    __shared__ float w[128*64];
    __shared__ float sc[64], sh[64], bb[128];
    int tid = threadIdx.x;
    for (int i = tid; i < 128*64; i += 128) w[i] = W3[i];
    if (tid < 64) { sc[tid] = g_sc[128+tid]; sh[tid] = g_sc[192+tid]; }
    if (tid < 128) bb[tid] = b3[tid];
    __syncthreads();
    int pos = blockIdx.x*128 + tid;
    float h[64];
    #pragma unroll
    for (int o = 0; o < 64; o++) {
        float y = g_buf[(size_t)o*PP + pos];
        h[o] = fmaxf(fmaf(y, sc[o], sh[o]), 0.f);
    }
    int lane = tid & 15;
    int q = pos >> 4;
    int b = q >> 11, qq = q & 2047;
    for (int c = 0; c < 4; c++) {
        float acc[32];
        #pragma unroll
        for (int o = 0; o < 32; o++) {
            const float* wr = w + (c*32 + o)*64;
            float a = bb[c*32 + o];
            #pragma unroll
            for (int f = 0; f < 64; f++) a = fmaf(wr[f], h[f], a);
            acc[o] = a;
        }
        #pragma unroll
        for (int o = 0; o < 32; o++) {
            float v = acc[o];
            #pragma unroll
            for (int off = 1; off < 16; off <<= 1)
                v = fmaxf(v, __shfl_xor_sync(0xffffffffu, v, off));
            acc[o] = v;
        }
        #pragma unroll
        for (int o = 0; o < 32; o++)
            if ((o & 15) == lane)
                outf[((size_t)b*128 + c*32 + o)*NP + qq] = acc[o];
    }
}

extern "C" void kernel_launch(void* const* d_in, const int* in_sizes, int n_in,
                              void* d_out, int out_size) {
    const float* xyz = (const float*)d_in[0];
    const float* pts = (const float*)d_in[1];
    const float* W1  = (const float*)d_in[2];
    const float* b1  = (const float*)d_in[3];
    const float* g1  = (const float*)d_in[4];
    const float* be1 = (const float*)d_in[5];
    const float* W2  = (const float*)d_in[6];
    const float* b2  = (const float*)d_in[7];
    const float* g2  = (const float*)d_in[8];
    const float* be2 = (const float*)d_in[9];
    const float* W3  = (const float*)d_in[10];
    const float* b3  = (const float*)d_in[11];
    float* out  = (float*)d_out;
    float* onx  = out;
    float* ofe  = out + (size_t)BB*3*NP;

    const int FPS_SM = (3*NN + 64)*4;
    cudaFuncSetAttribute(k_fps, cudaFuncAttributeMaxDynamicSharedMemorySize, FPS_SM);

    k_zero<<<1, 256>>>();
    k_fps<<<BB, 512, FPS_SM>>>(xyz);
    k_nx<<<(BB*NP)/256, 256>>>(xyz, onx);
    k_knn<<<dim3(NP/8, BB), 256>>>(xyz);
    k_z1<<<PTSN/128, 128>>>(pts, W1);
    k_p1<<<PP/128, 128>>>(xyz, W1, b1, onx);
    k_st<<<dim3(16, 64), 256>>>(0);
    k_fin<<<1, 64>>>(g1, be1, 0);
    k_p2<<<PP/128, 128>>>(W2, b2);
    k_st<<<dim3(16, 64), 256>>>(1);
    k_fin<<<1, 64>>>(g2, be2, 1);
    k_p3<<<PP/128, 128>>>(W3, b3, ofe);
}

// round 6
// speedup vs baseline: 2.2149x; 1.6021x over previous
#include <cuda_runtime.h>

#define BB 8
#define NN 8192
#define NP 2048
#define KK 16
#define FF 64
#define PP (BB*NP*KK)
#define PTSN (BB*NN)

typedef unsigned long long ull;
typedef unsigned int uint;

__device__ float g_Z1[(size_t)PTSN*FF];
__device__ float g_buf[(size_t)PP*FF];
__device__ int   g_fps[BB*NP];
__device__ int   g_knn[PP];
__device__ float g_stats[256];
__device__ float g_sc[256];

__global__ void k_zero() { g_stats[threadIdx.x] = 0.f; }

// ---- packed f32x2 helpers (per-lane IEEE rn, identical to scalar) ----
__device__ __forceinline__ ull pk2(float lo, float hi) {
    ull r; asm("mov.b64 %0, {%1,%2};" : "=l"(r) : "f"(lo), "f"(hi)); return r;
}
__device__ __forceinline__ void upk2(ull v, float& lo, float& hi) {
    asm("mov.b64 {%0,%1}, %2;" : "=f"(lo), "=f"(hi) : "l"(v));
}
__device__ __forceinline__ ull add2(ull a, ull b) {
    ull r; asm("add.rn.f32x2 %0, %1, %2;" : "=l"(r) : "l"(a), "l"(b)); return r;
}
__device__ __forceinline__ ull mul2(ull a, ull b) {
    ull r; asm("mul.rn.f32x2 %0, %1, %2;" : "=l"(r) : "l"(a), "l"(b)); return r;
}

// ---------------- FPS: one block per batch, 256 thr x 32 pts, REDUX reductions ----------------
__global__ __launch_bounds__(256) void k_fps(const float* __restrict__ xyz) {
    extern __shared__ float sm[];
    float* sx = sm; float* sy = sm + NN; float* sz = sm + 2*NN;
    uint* rvu = (uint*)(sm + 3*NN);     // 16 (double-buffered 2x8)
    int*  ri  = (int*)(rvu + 16);       // 16

    int b = blockIdx.x, tid = threadIdx.x, lane = tid & 31, wid = tid >> 5;
    int base = tid*32;
    const float* X = xyz + (size_t)b*3*NN;

    ull xp[16], yp[16], zp[16];
    float dmin[32];
    #pragma unroll
    for (int i = 0; i < 32; i += 4) {
        float4 vx = *(const float4*)(X + base + i);
        float4 vy = *(const float4*)(X + NN + base + i);
        float4 vz = *(const float4*)(X + 2*NN + base + i);
        xp[i/2]   = pk2(vx.x, vx.y); xp[i/2+1] = pk2(vx.z, vx.w);
        yp[i/2]   = pk2(vy.x, vy.y); yp[i/2+1] = pk2(vy.z, vy.w);
        zp[i/2]   = pk2(vz.x, vz.y); zp[i/2+1] = pk2(vz.z, vz.w);
        sx[base+i]=vx.x; sx[base+i+1]=vx.y; sx[base+i+2]=vx.z; sx[base+i+3]=vx.w;
        sy[base+i]=vy.x; sy[base+i+1]=vy.y; sy[base+i+2]=vy.z; sy[base+i+3]=vy.w;
        sz[base+i]=vz.x; sz[base+i+1]=vz.y; sz[base+i+2]=vz.z; sz[base+i+3]=vz.w;
    }
    #pragma unroll
    for (int i = 0; i < 32; i++) dmin[i] = 1e10f;

    float px = X[0], py = X[NN], pz = X[2*NN];
    if (tid == 0) g_fps[b*NP] = 0;
    __syncthreads();

    for (int t = 1; t < NP; t++) {
        ull npx = pk2(-px, -px), npy = pk2(-py, -py), npz = pk2(-pz, -pz);
        float bestv = 0.f; int besti = 0x7fffffff;
        #pragma unroll
        for (int j = 0; j < 16; j++) {
            ull dx = add2(xp[j], npx);
            ull dy = add2(yp[j], npy);
            ull dz = add2(zp[j], npz);
            ull d2 = add2(add2(mul2(dx,dx), mul2(dy,dy)), mul2(dz,dz));
            float d0, d1; upk2(d2, d0, d1);
            int i0 = 2*j, i1 = 2*j + 1;
            dmin[i0] = fminf(dmin[i0], d0);
            if (dmin[i0] > bestv) { bestv = dmin[i0]; besti = base + i0; }
            dmin[i1] = fminf(dmin[i1], d1);
            if (dmin[i1] > bestv) { bestv = dmin[i1]; besti = base + i1; }
        }
        // warp argmax via REDUX (dmin >= 0 so float bits order as u32; ties -> lowest index)
        uint u  = __float_as_uint(bestv);
        uint um = __reduce_max_sync(0xffffffffu, u);
        uint wini = __reduce_min_sync(0xffffffffu, (u == um) ? (uint)besti : 0x7fffffffu);
        int bufo = (t & 1)*8;
        if (lane == 0) { rvu[bufo + wid] = um; ri[bufo + wid] = (int)wini; }
        __syncthreads();
        uint u2 = (lane < 8) ? rvu[bufo + lane] : 0u;
        int  j2 = (lane < 8) ? ri[bufo + lane]  : 0x7fffffff;
        uint um2 = __reduce_max_sync(0xffffffffu, u2);
        uint jw  = __reduce_min_sync(0xffffffffu, (u2 == um2) ? (uint)j2 : 0x7fffffffu);
        int win = (int)jw;
        px = sx[win]; py = sy[win]; pz = sz[win];
        if (tid == 0) g_fps[b*NP + t] = win;
    }
}

// ---------------- gather new_xyz ----------------
__global__ void k_nx(const float* __restrict__ xyz, float* __restrict__ out) {
    int i = blockIdx.x*256 + threadIdx.x;
    int b = i >> 11, q = i & 2047, n = g_fps[i];
    #pragma unroll
    for (int c = 0; c < 3; c++)
        out[((size_t)b*3 + c)*NP + q] = xyz[((size_t)b*3 + c)*NN + n];
}

// ---------------- KNN: warp top-32, float-threshold ballot, REDUX maintenance ----------------
__device__ __forceinline__ uint ordu(float d) {
    uint u = __float_as_uint(d);
    return u ^ (((uint)((int)u >> 31)) | 0x80000000u);
}
__device__ __forceinline__ float iordu(uint u) {
    uint v = (u & 0x80000000u) ? (u ^ 0x80000000u) : ~u;
    return __uint_as_float(v);
}

__global__ __launch_bounds__(256) void k_knn(const float* __restrict__ xyz) {
    __shared__ float4 s4[2048];
    int b = blockIdx.y, tid = threadIdx.x, lane = tid & 31, w = tid >> 5;
    const float* X = xyz + (size_t)b*3*NN;
    int q = blockIdx.x*8 + w;
    int qi = g_fps[b*NP + q];
    float qx = X[qi], qy = X[NN+qi], qz = X[2*NN+qi];
    float qq = __fadd_rn(__fadd_rn(__fmul_rn(qx,qx), __fmul_rn(qy,qy)), __fmul_rn(qz,qz));

    // load tile 0
    for (int j = tid; j < 2048; j += 256) {
        float xx = X[j], yy = X[NN+j], zz = X[2*NN+j];
        float r = __fadd_rn(__fadd_rn(__fmul_rn(xx,xx), __fmul_rn(yy,yy)), __fmul_rn(zz,zz));
        s4[j] = make_float4(xx, yy, zz, r);
    }
    __syncthreads();

    uint hu; int hj;         // this lane's held (ordered dist, index)
    uint um; int jm;         // warp max key
    int wlane; float wd;     // holder lane, float threshold

    {   // init: first 32 candidates fill the held set exactly
        float4 c = s4[lane];
        float dot = __fadd_rn(__fadd_rn(__fmul_rn(qx,c.x), __fmul_rn(qy,c.y)), __fmul_rn(qz,c.z));
        float d = __fsub_rn(__fadd_rn(qq, c.w), __fmul_rn(2.0f, dot));
        hu = ordu(d); hj = lane;
        um = __reduce_max_sync(0xffffffffu, hu);
        jm = (int)__reduce_max_sync(0xffffffffu, (hu == um) ? (uint)hj : 0u);
        uint bal = __ballot_sync(0xffffffffu, hu == um && hj == jm);
        wlane = __ffs(bal) - 1;
        wd = iordu(um);
    }

    for (int tile = 0; tile < NN; tile += 2048) {
        if (tile) {
            __syncthreads();
            for (int j = tid; j < 2048; j += 256) {
                int g = tile + j;
                float xx = X[g], yy = X[NN+g], zz = X[2*NN+g];
                float r = __fadd_rn(__fadd_rn(__fmul_rn(xx,xx), __fmul_rn(yy,yy)), __fmul_rn(zz,zz));
                s4[j] = make_float4(xx, yy, zz, r);
            }
            __syncthreads();
        }
        for (int k = (tile == 0 ? 32 : 0); k < 2048; k += 32) {
            float4 c = s4[k + lane];
            float dot = __fadd_rn(__fadd_rn(__fmul_rn(qx,c.x), __fmul_rn(qy,c.y)), __fmul_rn(qz,c.z));
            float d = __fsub_rn(__fadd_rn(qq, c.w), __fmul_rn(2.0f, dot));
            uint m = __ballot_sync(0xffffffffu, d <= wd);
            while (m) {
                int src = __ffs(m) - 1; m &= m - 1;
                float cd = __shfl_sync(0xffffffffu, d, src);
                int cj = tile + k + src;
                uint cu = ordu(cd);
                if (cu < um || (cu == um && cj < jm)) {     // exact key compare
                    if (lane == wlane) { hu = cu; hj = cj; }
                    um = __reduce_max_sync(0xffffffffu, hu);
                    jm = (int)__reduce_max_sync(0xffffffffu, (hu == um) ? (uint)hj : 0u);
                    uint bal = __ballot_sync(0xffffffffu, hu == um && hj == jm);
                    wlane = __ffs(bal) - 1;
                    wd = iordu(um);
                }
            }
        }
    }
    // extract 16 smallest keys ascending (dist asc, ties -> lower index)
    int outidx = 0;
    #pragma unroll
    for (int r = 0; r < KK; r++) {
        uint mu = __reduce_min_sync(0xffffffffu, hu);
        uint mj = __reduce_min_sync(0xffffffffu, (hu == mu) ? (uint)hj : 0x7fffffffu);
        if (lane == r) outidx = (int)mj;
        if (hu == mu && hj == (int)mj) { hu = 0xffffffffu; hj = 0x7fffffff; }
    }
    if (lane < KK) g_knn[((size_t)b*NP + q)*KK + lane] = outidx;
}

// ---------------- Z1 = W1[:,3:] @ points, per point ----------------
__global__ __launch_bounds__(128) void k_z1(const float* __restrict__ pts,
                                            const float* __restrict__ W1) {
    __shared__ float w[FF*FF];
    int tid = threadIdx.x;
    for (int i = tid; i < FF*FF; i += 128) w[i] = W1[(i>>6)*67 + 3 + (i&63)];
    __syncthreads();
    int p = blockIdx.x*128 + tid;
    int b = p >> 13, n = p & (NN-1);
    float xv[FF];
    #pragma unroll
    for (int f = 0; f < FF; f++) xv[f] = pts[((size_t)b*FF + f)*NN + n];
    float* zr = g_Z1 + (size_t)p*FF;
    for (int o = 0; o < FF; o += 4) {
        float a0=0.f, a1=0.f, a2=0.f, a3=0.f;
        #pragma unroll
        for (int f = 0; f < FF; f++) {
            float xf = xv[f];
            a0 = fmaf(w[(o+0)*FF+f], xf, a0);
            a1 = fmaf(w[(o+1)*FF+f], xf, a1);
            a2 = fmaf(w[(o+2)*FF+f], xf, a2);
            a3 = fmaf(w[(o+3)*FF+f], xf, a3);
        }
        *(float4*)(zr + o) = make_float4(a0, a1, a2, a3);
    }
}

// ---------------- pass1: y1 -> g_buf channel-major ----------------
__global__ __launch_bounds__(128) void k_p1(const float* __restrict__ xyz,
                                            const float* __restrict__ W1,
                                            const float* __restrict__ b1,
                                            const float* __restrict__ nxyz) {
    __shared__ float w0[64], w1s[64], w2s[64], bb[64];
    int tid = threadIdx.x;
    if (tid < 64) {
        w0[tid]  = W1[tid*67 + 0]; w1s[tid] = W1[tid*67 + 1];
        w2s[tid] = W1[tid*67 + 2]; bb[tid]  = b1[tid];
    }
    __syncthreads();
    int pos = blockIdx.x*128 + tid;
    int b = pos >> 15, q = (pos >> 4) & 2047, n = g_knn[pos];
    float cx = nxyz[((size_t)b*3+0)*NP+q], cy = nxyz[((size_t)b*3+1)*NP+q], cz = nxyz[((size_t)b*3+2)*NP+q];
    const float* X = xyz + (size_t)b*3*NN;
    float dx = X[n]-cx, dy = X[NN+n]-cy, dz = X[2*NN+n]-cz;
    const float4* zr = (const float4*)(g_Z1 + (size_t)(b*NN + n)*FF);
    #pragma unroll
    for (int i = 0; i < 16; i++) {
        float4 v = zr[i]; int o = 4*i;
        g_buf[(size_t)(o+0)*PP+pos] = fmaf(w2s[o+0],dz, fmaf(w1s[o+0],dy, fmaf(w0[o+0],dx, v.x+bb[o+0])));
        g_buf[(size_t)(o+1)*PP+pos] = fmaf(w2s[o+1],dz, fmaf(w1s[o+1],dy, fmaf(w0[o+1],dx, v.y+bb[o+1])));
        g_buf[(size_t)(o+2)*PP+pos] = fmaf(w2s[o+2],dz, fmaf(w1s[o+2],dy, fmaf(w0[o+2],dx, v.z+bb[o+2])));
        g_buf[(size_t)(o+3)*PP+pos] = fmaf(w2s[o+3],dz, fmaf(w1s[o+3],dy, fmaf(w0[o+3],dx, v.w+bb[o+3])));
    }
}

// ---------------- per-channel sum/sumsq ----------------
__global__ __launch_bounds__(256) void k_st(int which) {
    int o = blockIdx.y;
    const float* src = g_buf + (size_t)o*PP + blockIdx.x*(PP/16);
    float s = 0.f, s2 = 0.f;
    for (int i = threadIdx.x; i < PP/16; i += 256) {
        float v = src[i]; s += v; s2 = fmaf(v, v, s2);
    }
    #pragma unroll
    for (int off = 16; off; off >>= 1) {
        s  += __shfl_down_sync(0xffffffffu, s,  off);
        s2 += __shfl_down_sync(0xffffffffu, s2, off);
    }
    __shared__ float as[8], as2[8];
    int wid = threadIdx.x >> 5;
    if ((threadIdx.x & 31) == 0) { as[wid] = s; as2[wid] = s2; }
    __syncthreads();
    if (threadIdx.x == 0) {
        float ts = 0.f, ts2 = 0.f;
        #pragma unroll
        for (int w = 0; w < 8; w++) { ts += as[w]; ts2 += as2[w]; }
        atomicAdd(g_stats + which*128 + o, ts);
        atomicAdd(g_stats + which*128 + 64 + o, ts2);
    }
}

__global__ void k_fin(const float* __restrict__ gam, const float* __restrict__ bet, int which) {
    int o = threadIdx.x;
    float m = g_stats[which*128 + o] / (float)PP;
    float v = g_stats[which*128 + 64 + o] / (float)PP - m*m;
    v = fmaxf(v, 0.f);
    float sc = gam[o] * rsqrtf(v + 1e-5f);
    g_sc[which*128 + o] = sc;
    g_sc[which*128 + 64 + o] = bet[o] - m*sc;
}

// ---------------- pass2: bn1+relu -> conv2 (in place) ----------------
__global__ __launch_bounds__(128) void k_p2(const float* __restrict__ W2, const float* __restrict__ b2) {
    __shared__ float w[64*64];
    __shared__ float sc[64], sh[64], bb[64];
    int tid = threadIdx.x;
    for (int i = tid; i < 64*64; i += 128) w[i] = W2[i];
    if (tid < 64) { sc[tid] = g_sc[tid]; sh[tid] = g_sc[64+tid]; bb[tid] = b2[tid]; }
    __syncthreads();
    int pos = blockIdx.x*128 + tid;
    float h[64];
    #pragma unroll
    for (int o = 0; o < 64; o++) {
        float y = g_buf[(size_t)o*PP + pos];
        h[o] = fmaxf(fmaf(y, sc[o], sh[o]), 0.f);
    }
    for (int o = 0; o < 64; o++) {
        float a = bb[o];
        const float* wr = w + o*64;
        #pragma unroll
        for (int f = 0; f < 64; f++) a = fmaf(wr[f], h[f], a);
        g_buf[(size_t)o*PP + pos] = a;
    }
}

// ---------------- pass3: bn2+relu -> conv3 -> max over K ----------------
__global__ __launch_bounds__(128) void k_p3(const float* __restrict__ W3, const float* __restrict__ b3,
                                            float* __restrict__ outf) {
    __shared__ float w[128*64];
    __shared__ float sc[64], sh[64], bb[128];
    int tid = threadIdx.x;
    for (int i = tid; i < 128*64; i += 128) w[i] = W3[i];
    if (tid < 64) { sc[tid] = g_sc[128+tid]; sh[tid] = g_sc[192+tid]; }
    if (tid < 128) bb[tid] = b3[tid];
    __syncthreads();
    int pos = blockIdx.x*128 + tid;
    float h[64];
    #pragma unroll
    for (int o = 0; o < 64; o++) {
        float y = g_buf[(size_t)o*PP + pos];
        h[o] = fmaxf(fmaf(y, sc[o], sh[o]), 0.f);
    }
    int lane = tid & 15;
    int q = pos >> 4;
    int b = q >> 11, qq = q & 2047;
    for (int c = 0; c < 4; c++) {
        float acc[32];
        #pragma unroll
        for (int o = 0; o < 32; o++) {
            const float* wr = w + (c*32 + o)*64;
            float a = bb[c*32 + o];
            #pragma unroll
            for (int f = 0; f < 64; f++) a = fmaf(wr[f], h[f], a);
            acc[o] = a;
        }
        #pragma unroll
        for (int o = 0; o < 32; o++) {
            float v = acc[o];
            #pragma unroll
            for (int off = 1; off < 16; off <<= 1)
                v = fmaxf(v, __shfl_xor_sync(0xffffffffu, v, off));
            acc[o] = v;
        }
        #pragma unroll
        for (int o = 0; o < 32; o++)
            if ((o & 15) == lane)
                outf[((size_t)b*128 + c*32 + o)*NP + qq] = acc[o];
    }
}

extern "C" void kernel_launch(void* const* d_in, const int* in_sizes, int n_in,
                              void* d_out, int out_size) {
    const float* xyz = (const float*)d_in[0];
    const float* pts = (const float*)d_in[1];
    const float* W1  = (const float*)d_in[2];
    const float* b1  = (const float*)d_in[3];
    const float* g1  = (const float*)d_in[4];
    const float* be1 = (const float*)d_in[5];
    const float* W2  = (const float*)d_in[6];
    const float* b2  = (const float*)d_in[7];
    const float* g2  = (const float*)d_in[8];
    const float* be2 = (const float*)d_in[9];
    const float* W3  = (const float*)d_in[10];
    const float* b3  = (const float*)d_in[11];
    float* out  = (float*)d_out;
    float* onx  = out;
    float* ofe  = out + (size_t)BB*3*NP;

    const int FPS_SM = (3*NN + 32)*4;
    cudaFuncSetAttribute(k_fps, cudaFuncAttributeMaxDynamicSharedMemorySize, FPS_SM);

    k_zero<<<1, 256>>>();
    k_fps<<<BB, 256, FPS_SM>>>(xyz);
    k_nx<<<(BB*NP)/256, 256>>>(xyz, onx);
    k_knn<<<dim3(NP/8, BB), 256>>>(xyz);
    k_z1<<<PTSN/128, 128>>>(pts, W1);
    k_p1<<<PP/128, 128>>>(xyz, W1, b1, onx);
    k_st<<<dim3(16, 64), 256>>>(0);
    k_fin<<<1, 64>>>(g1, be1, 0);
    k_p2<<<PP/128, 128>>>(W2, b2);
    k_st<<<dim3(16, 64), 256>>>(1);
    k_fin<<<1, 64>>>(g2, be2, 1);
    k_p3<<<PP/128, 128>>>(W3, b3, ofe);
}